// round 1
// baseline (speedup 1.0000x reference)
#include <cuda_runtime.h>
#include <cuda_bf16.h>
#include <math.h>

#define N_CNT 10000
#define E_CNT 30000
#define D_IN 64
#define EDIM 16
#define H1 128
#define H2 64
#define C_OUT 10

// Extended B matrices: bias folded in as extra columns
#define NB1 1088   // 16*64 + 64 (be1 columns)
#define NB2 170    // 16*10 + 10 (be2 columns)

// ---------------- scratch (static device memory; no allocations) ------------
__device__ int   g_is64;
__device__ int   g_src[E_CNT];
__device__ int   g_dst[E_CNT];
__device__ float g_B1[H1 * NB1];            // [128][1088]
__device__ float g_B2[H2 * NB2];            // [64][170]
__device__ float g_h [N_CNT * H1];          // [10000][128]
__device__ float g_P1[(size_t)N_CNT * NB1]; // [10000][1088]  ~43.5MB
__device__ float g_agg1[N_CNT * H2];        // [10000][64]
__device__ float g_h2 [N_CNT * H2];         // [10000][64]
__device__ float g_P2[(size_t)N_CNT * NB2]; // [10000][170]
__device__ float g_agg2[N_CNT * C_OUT];     // [10000][10]

// ---------------- index dtype detection + normalization ---------------------
__global__ void detect_idx_kernel(const int* ei) {
    __shared__ int cnt;
    if (threadIdx.x == 0) cnt = 0;
    __syncthreads();
    int z = 0;
    for (int i = threadIdx.x; i < 1024; i += blockDim.x)
        if (ei[2 * i + 1] == 0) z++;
    atomicAdd(&cnt, z);
    __syncthreads();
    if (threadIdx.x == 0) g_is64 = (cnt > 900) ? 1 : 0;
}

__global__ void convert_idx_kernel(const void* eidx) {
    int i = blockIdx.x * blockDim.x + threadIdx.x;
    if (i >= E_CNT) return;
    if (g_is64) {
        const long long* q = (const long long*)eidx;
        g_src[i] = (int)q[i];
        g_dst[i] = (int)q[E_CNT + i];
    } else {
        const int* q = (const int*)eidx;
        g_src[i] = q[i];
        g_dst[i] = q[E_CNT + i];
    }
}

// ---------------- build permuted edge-MLP weights ----------------------------
// B1[i][k*64+o] = We1[k][i*64+o];  B1[i][1024+o] = be1[i*64+o]
__global__ void build_B1_kernel(const float* __restrict__ We1,
                                const float* __restrict__ be1) {
    int idx = blockIdx.x * blockDim.x + threadIdx.x;
    if (idx >= H1 * NB1) return;
    int i = idx / NB1, col = idx - i * NB1;
    float v;
    if (col < EDIM * H2) {
        int k = col >> 6, o = col & 63;
        v = We1[(size_t)k * (H1 * H2) + i * H2 + o];
    } else {
        v = be1[(size_t)i * H2 + (col - EDIM * H2)];
    }
    g_B1[idx] = v;
}

// B2[i][k*10+c] = We2[k][i*10+c];  B2[i][160+c] = be2[i*10+c]
__global__ void build_B2_kernel(const float* __restrict__ We2,
                                const float* __restrict__ be2) {
    int idx = blockIdx.x * blockDim.x + threadIdx.x;
    if (idx >= H2 * NB2) return;
    int i = idx / NB2, col = idx - i * NB2;
    float v;
    if (col < EDIM * C_OUT) {
        int k = col / C_OUT, c = col - k * C_OUT;
        v = We2[(size_t)k * (H2 * C_OUT) + i * C_OUT + c];
    } else {
        v = be2[(size_t)i * C_OUT + (col - EDIM * C_OUT)];
    }
    g_B2[idx] = v;
}

// ---------------- generic fp32 tiled GEMM with epilogue ----------------------
// EPI 0: C = A@B
// EPI 1: C = relu(A@B + bias)
// EPI 2: C = relu(A@B + bias + addend)
#define BM 64
#define BN 64
#define BK 16

template <int EPI>
__global__ void gemm_ep(const float* __restrict__ A, const float* __restrict__ B,
                        float* __restrict__ Cmat, const float* __restrict__ bias,
                        const float* __restrict__ addend, int M, int Nn, int K) {
    __shared__ float As[BK][BM];
    __shared__ float Bs[BK][BN + 4];
    int tid = threadIdx.x;
    int tx = tid & 15, ty = tid >> 4;
    int row0 = blockIdx.y * BM;
    int col0 = blockIdx.x * BN;
    float acc[4][4] = {};

    for (int k0 = 0; k0 < K; k0 += BK) {
        for (int idx = tid; idx < BM * BK; idx += 256) {
            int m = idx >> 4, k = idx & 15;
            int r = row0 + m;
            As[k][m] = (r < M) ? A[(size_t)r * K + k0 + k] : 0.f;
        }
        for (int idx = tid; idx < BK * BN; idx += 256) {
            int k = idx >> 6, n = idx & 63;
            int c = col0 + n;
            Bs[k][n] = (c < Nn) ? B[(size_t)(k0 + k) * Nn + c] : 0.f;
        }
        __syncthreads();
#pragma unroll
        for (int k = 0; k < BK; k++) {
            float4 av = *reinterpret_cast<const float4*>(&As[k][ty * 4]);
            float4 bv = *reinterpret_cast<const float4*>(&Bs[k][tx * 4]);
            float a[4] = {av.x, av.y, av.z, av.w};
            float b[4] = {bv.x, bv.y, bv.z, bv.w};
#pragma unroll
            for (int r = 0; r < 4; r++)
#pragma unroll
                for (int s = 0; s < 4; s++)
                    acc[r][s] = fmaf(a[r], b[s], acc[r][s]);
        }
        __syncthreads();
    }

#pragma unroll
    for (int r = 0; r < 4; r++) {
        int rr = row0 + ty * 4 + r;
        if (rr >= M) continue;
#pragma unroll
        for (int s = 0; s < 4; s++) {
            int cc = col0 + tx * 4 + s;
            if (cc >= Nn) continue;
            float v = acc[r][s];
            if (EPI >= 1) v += bias[cc];
            if (EPI == 2) v += addend[(size_t)rr * Nn + cc];
            if (EPI >= 1) v = fmaxf(v, 0.f);
            Cmat[(size_t)rr * Nn + cc] = v;
        }
    }
}

// ---------------- edge pass 1: msg = ea @ P1[src] slices, scatter to agg1 ----
__global__ void edge_pass1(const float* __restrict__ ea) {
    int le = threadIdx.x >> 6;              // 0..3 local edge
    int o  = threadIdx.x & 63;
    int e  = blockIdx.x * 4 + le;
    __shared__ float sea[4][EDIM];
    if (e < E_CNT && o < EDIM) sea[le][o] = ea[(size_t)e * EDIM + o];
    __syncthreads();
    if (e >= E_CNT) return;
    int s = g_src[e], d = g_dst[e];
    const float* Prow = g_P1 + (size_t)s * NB1;
    float acc = Prow[EDIM * H2 + o];        // be1 contribution
#pragma unroll
    for (int k = 0; k < EDIM; k++)
        acc = fmaf(sea[le][k], Prow[k * H2 + o], acc);
    atomicAdd(&g_agg1[(size_t)d * H2 + o], acc);
}

// ---------------- edge pass 2 ------------------------------------------------
__global__ void edge_pass2(const float* __restrict__ ea) {
    int t = blockIdx.x * blockDim.x + threadIdx.x;
    if (t >= E_CNT * C_OUT) return;
    int e = t / C_OUT, c = t - e * C_OUT;
    int s = g_src[e], d = g_dst[e];
    const float* Prow = g_P2 + (size_t)s * NB2;
    float acc = Prow[EDIM * C_OUT + c];     // be2 contribution
#pragma unroll
    for (int k = 0; k < EDIM; k++)
        acc = fmaf(ea[(size_t)e * EDIM + k], Prow[k * C_OUT + c], acc);
    atomicAdd(&g_agg2[(size_t)d * C_OUT + c], acc);
}

// ---------------- final: z = agg2 + h2@root2 + bias2; log_softmax ------------
__global__ void final_kernel(const float* __restrict__ root2,
                             const float* __restrict__ bias2,
                             float* __restrict__ out) {
    int n = blockIdx.x * blockDim.x + threadIdx.x;
    if (n >= N_CNT) return;
    float z[C_OUT];
#pragma unroll
    for (int c = 0; c < C_OUT; c++) z[c] = g_agg2[(size_t)n * C_OUT + c] + bias2[c];
    const float* hrow = g_h2 + (size_t)n * H2;
    for (int i = 0; i < H2; i++) {
        float hv = hrow[i];
#pragma unroll
        for (int c = 0; c < C_OUT; c++)
            z[c] = fmaf(hv, root2[i * C_OUT + c], z[c]);
    }
    float m = z[0];
#pragma unroll
    for (int c = 1; c < C_OUT; c++) m = fmaxf(m, z[c]);
    float sum = 0.f;
#pragma unroll
    for (int c = 0; c < C_OUT; c++) sum += expf(z[c] - m);
    float lse = m + logf(sum);
#pragma unroll
    for (int c = 0; c < C_OUT; c++) out[(size_t)n * C_OUT + c] = z[c] - lse;
}

// ---------------- launch -----------------------------------------------------
extern "C" void kernel_launch(void* const* d_in, const int* in_sizes, int n_in,
                              void* d_out, int out_size) {
    const float* x     = (const float*)d_in[0];
    const float* ea    = (const float*)d_in[1];
    const void*  eidx  = d_in[2];
    const float* W1    = (const float*)d_in[3];
    const float* b1    = (const float*)d_in[4];
    const float* We1   = (const float*)d_in[5];
    const float* be1   = (const float*)d_in[6];
    const float* root1 = (const float*)d_in[7];
    const float* bias1 = (const float*)d_in[8];
    const float* We2   = (const float*)d_in[9];
    const float* be2   = (const float*)d_in[10];
    const float* root2 = (const float*)d_in[11];
    const float* bias2 = (const float*)d_in[12];
    float* out = (float*)d_out;

    // resolve device symbol addresses (host-side, no allocation)
    void* p_agg1 = nullptr; void* p_agg2 = nullptr;
    float* ph = nullptr; float* ph2 = nullptr; float* pP1 = nullptr; float* pP2 = nullptr;
    float* pB1 = nullptr; float* pB2 = nullptr;
    cudaGetSymbolAddress(&p_agg1, g_agg1);
    cudaGetSymbolAddress(&p_agg2, g_agg2);
    cudaGetSymbolAddress((void**)&ph,  g_h);
    cudaGetSymbolAddress((void**)&ph2, g_h2);
    cudaGetSymbolAddress((void**)&pP1, g_P1);
    cudaGetSymbolAddress((void**)&pP2, g_P2);
    cudaGetSymbolAddress((void**)&pB1, g_B1);
    cudaGetSymbolAddress((void**)&pB2, g_B2);

    // index normalization
    detect_idx_kernel<<<1, 256>>>((const int*)eidx);
    convert_idx_kernel<<<(E_CNT + 255) / 256, 256>>>(eidx);

    // permuted weight builds (independent)
    build_B1_kernel<<<(H1 * NB1 + 255) / 256, 256>>>(We1, be1);
    build_B2_kernel<<<(H2 * NB2 + 255) / 256, 256>>>(We2, be2);

    // zero accumulators early
    cudaMemsetAsync(p_agg1, 0, (size_t)N_CNT * H2 * sizeof(float));
    cudaMemsetAsync(p_agg2, 0, (size_t)N_CNT * C_OUT * sizeof(float));

    dim3 blk(256);
    // h = relu(x @ W1 + b1)   [10000,128]
    {
        dim3 grid((H1 + BN - 1) / BN, (N_CNT + BM - 1) / BM);
        gemm_ep<1><<<grid, blk>>>(x, W1, ph, b1, nullptr, N_CNT, H1, D_IN);
    }
    // P1 = h @ B1   [10000,1088]
    {
        dim3 grid((NB1 + BN - 1) / BN, (N_CNT + BM - 1) / BM);
        gemm_ep<0><<<grid, blk>>>(ph, pB1, pP1, nullptr, nullptr, N_CNT, NB1, H1);
    }
    // edge pass 1 -> agg1
    edge_pass1<<<(E_CNT + 3) / 4, 256>>>(ea);
    // h2 = relu(h @ root1 + bias1 + agg1)
    {
        dim3 grid((H2 + BN - 1) / BN, (N_CNT + BM - 1) / BM);
        gemm_ep<2><<<grid, blk>>>(ph, root1, ph2, bias1, (const float*)p_agg1,
                                  N_CNT, H2, H1);
    }
    // P2 = h2 @ B2   [10000,170]
    {
        dim3 grid((NB2 + BN - 1) / BN, (N_CNT + BM - 1) / BM);
        gemm_ep<0><<<grid, blk>>>(ph2, pB2, pP2, nullptr, nullptr, N_CNT, NB2, H2);
    }
    // edge pass 2 -> agg2
    edge_pass2<<<(E_CNT * C_OUT + 255) / 256, 256>>>(ea);
    // final: z + log_softmax
    final_kernel<<<(N_CNT + 255) / 256, 256>>>(root2, bias2, out);
}

// round 2
// speedup vs baseline: 1.2418x; 1.2418x over previous
#include <cuda_runtime.h>
#include <cuda_bf16.h>
#include <math.h>

#define N_CNT 10000
#define E_CNT 30000
#define D_IN 64
#define EDIM 16
#define H1 128
#define H2 64
#define C_OUT 10

#define NB1 1088   // 16*64 + 64 (be1 columns folded in)
#define NB2 170    // 16*10 + 10 (be2 columns folded in)

// ---------------- scratch (static device memory; no allocations) ------------
__device__ int   g_is64;
__device__ int   g_src[E_CNT];
__device__ int   g_dst[E_CNT];
__device__ float g_B1[H1 * NB1];
__device__ float g_B2[H2 * NB2];
__device__ float g_h [N_CNT * H1];
__device__ float g_P1[(size_t)N_CNT * NB1];  // ~43.5MB (fits L2)
__device__ float g_agg1[N_CNT * H2];
__device__ float g_h2 [N_CNT * H2];
__device__ float g_P2[(size_t)N_CNT * NB2];
__device__ float g_agg2[N_CNT * C_OUT];

// ---------------- index dtype detection + normalization ---------------------
__global__ void detect_idx_kernel(const int* ei) {
    __shared__ int cnt;
    if (threadIdx.x == 0) cnt = 0;
    __syncthreads();
    int z = 0;
    for (int i = threadIdx.x; i < 1024; i += blockDim.x)
        if (ei[2 * i + 1] == 0) z++;
    atomicAdd(&cnt, z);
    __syncthreads();
    if (threadIdx.x == 0) g_is64 = (cnt > 900) ? 1 : 0;
}

__global__ void convert_idx_kernel(const void* eidx) {
    int i = blockIdx.x * blockDim.x + threadIdx.x;
    if (i >= E_CNT) return;
    if (g_is64) {
        const long long* q = (const long long*)eidx;
        g_src[i] = (int)q[i];
        g_dst[i] = (int)q[E_CNT + i];
    } else {
        const int* q = (const int*)eidx;
        g_src[i] = q[i];
        g_dst[i] = q[E_CNT + i];
    }
}

// ---------------- build permuted edge-MLP weights ----------------------------
__global__ void build_B1_kernel(const float* __restrict__ We1,
                                const float* __restrict__ be1) {
    int idx = blockIdx.x * blockDim.x + threadIdx.x;
    if (idx >= H1 * NB1) return;
    int i = idx / NB1, col = idx - i * NB1;
    float v;
    if (col < EDIM * H2) {
        int k = col >> 6, o = col & 63;
        v = We1[(size_t)k * (H1 * H2) + i * H2 + o];
    } else {
        v = be1[(size_t)i * H2 + (col - EDIM * H2)];
    }
    g_B1[idx] = v;
}

__global__ void build_B2_kernel(const float* __restrict__ We2,
                                const float* __restrict__ be2) {
    int idx = blockIdx.x * blockDim.x + threadIdx.x;
    if (idx >= H2 * NB2) return;
    int i = idx / NB2, col = idx - i * NB2;
    float v;
    if (col < EDIM * C_OUT) {
        int k = col / C_OUT, c = col - k * C_OUT;
        v = We2[(size_t)k * (H2 * C_OUT) + i * C_OUT + c];
    } else {
        v = be2[(size_t)i * C_OUT + (col - EDIM * C_OUT)];
    }
    g_B2[idx] = v;
}

// ---------------- big SGEMM: 128x128 tile, 8x8/thread, BK=8, double-buffered -
// EPI 0: C = A@B        EPI 1: C = relu(A@B + bias)
#define GBM 128
#define GBN 128
#define GBK 8

template <int EPI>
__global__ __launch_bounds__(256, 2)
void gemm128(const float* __restrict__ A, const float* __restrict__ B,
             float* __restrict__ Cmat, const float* __restrict__ bias,
             int M, int Nn, int K) {
    __shared__ float As[2][GBK][GBM + 4];
    __shared__ float Bs[2][GBK][GBN];

    int tid = threadIdx.x;
    int tx = tid & 15, ty = tid >> 4;        // 16x16 thread grid
    int ty4 = ty * 4, tx4 = tx * 4;
    int row0 = blockIdx.y * GBM;
    int col0 = blockIdx.x * GBN;

    // global load mapping
    int arow = tid >> 1;                      // 0..127
    int akq  = (tid & 1) * 4;                 // 0 or 4
    int brow = tid >> 5;                      // 0..7
    int bcol = (tid & 31) * 4;                // 0..124

    int ga_row = row0 + arow;
    int gb_col = col0 + bcol;
    bool a_ok = (ga_row < M);
    bool b_ok = (gb_col < Nn);

    const float* Aptr = A + (size_t)(a_ok ? ga_row : 0) * K + akq;
    const float* Bptr = B + (size_t)brow * Nn + (b_ok ? gb_col : 0);

    float acc[8][8];
#pragma unroll
    for (int r = 0; r < 8; r++)
#pragma unroll
        for (int s = 0; s < 8; s++) acc[r][s] = 0.f;

    int nt = K / GBK;

    // prologue: tile 0
    {
        float4 ra = a_ok ? *reinterpret_cast<const float4*>(Aptr)
                         : make_float4(0.f, 0.f, 0.f, 0.f);
        float4 rb = b_ok ? *reinterpret_cast<const float4*>(Bptr)
                         : make_float4(0.f, 0.f, 0.f, 0.f);
        As[0][akq + 0][arow] = ra.x;
        As[0][akq + 1][arow] = ra.y;
        As[0][akq + 2][arow] = ra.z;
        As[0][akq + 3][arow] = ra.w;
        *reinterpret_cast<float4*>(&Bs[0][brow][bcol]) = rb;
    }
    __syncthreads();

    for (int kt = 0; kt < nt; kt++) {
        int cur = kt & 1;
        float4 ra, rb;
        bool pre = (kt + 1 < nt);
        if (pre) {
            int k0 = (kt + 1) * GBK;
            ra = a_ok ? *reinterpret_cast<const float4*>(Aptr + k0)
                      : make_float4(0.f, 0.f, 0.f, 0.f);
            rb = b_ok ? *reinterpret_cast<const float4*>(Bptr + (size_t)k0 * Nn)
                      : make_float4(0.f, 0.f, 0.f, 0.f);
        }
#pragma unroll
        for (int k = 0; k < GBK; k++) {
            float4 a0 = *reinterpret_cast<const float4*>(&As[cur][k][ty4]);
            float4 a1 = *reinterpret_cast<const float4*>(&As[cur][k][ty4 + 64]);
            float4 b0 = *reinterpret_cast<const float4*>(&Bs[cur][k][tx4]);
            float4 b1 = *reinterpret_cast<const float4*>(&Bs[cur][k][tx4 + 64]);
            float a[8] = {a0.x, a0.y, a0.z, a0.w, a1.x, a1.y, a1.z, a1.w};
            float b[8] = {b0.x, b0.y, b0.z, b0.w, b1.x, b1.y, b1.z, b1.w};
#pragma unroll
            for (int r = 0; r < 8; r++)
#pragma unroll
                for (int s = 0; s < 8; s++)
                    acc[r][s] = fmaf(a[r], b[s], acc[r][s]);
        }
        if (pre) {
            int nxt = cur ^ 1;
            As[nxt][akq + 0][arow] = ra.x;
            As[nxt][akq + 1][arow] = ra.y;
            As[nxt][akq + 2][arow] = ra.z;
            As[nxt][akq + 3][arow] = ra.w;
            *reinterpret_cast<float4*>(&Bs[nxt][brow][bcol]) = rb;
            __syncthreads();
        }
    }

    // epilogue
#pragma unroll
    for (int r = 0; r < 8; r++) {
        int rr = row0 + ty4 + (r & 3) + ((r >> 2) << 6);
        if (rr >= M) continue;
        float* crow = Cmat + (size_t)rr * Nn;
#pragma unroll
        for (int s = 0; s < 8; s++) {
            int cc = col0 + tx4 + (s & 3) + ((s >> 2) << 6);
            if (cc >= Nn) continue;
            float v = acc[r][s];
            if (EPI == 1) v = fmaxf(v + bias[cc], 0.f);
            crow[cc] = v;
        }
    }
}

// ---------------- small fp32 tiled GEMM with epilogue ------------------------
// EPI 0: C = A@B   EPI 2: C = relu(A@B + bias + addend)
#define BM 64
#define BN 64
#define BK 16

template <int EPI>
__global__ void gemm_ep(const float* __restrict__ A, const float* __restrict__ B,
                        float* __restrict__ Cmat, const float* __restrict__ bias,
                        const float* __restrict__ addend, int M, int Nn, int K) {
    __shared__ float As[BK][BM];
    __shared__ float Bs[BK][BN + 4];
    int tid = threadIdx.x;
    int tx = tid & 15, ty = tid >> 4;
    int row0 = blockIdx.y * BM;
    int col0 = blockIdx.x * BN;
    float acc[4][4] = {};

    for (int k0 = 0; k0 < K; k0 += BK) {
        for (int idx = tid; idx < BM * BK; idx += 256) {
            int m = idx >> 4, k = idx & 15;
            int r = row0 + m;
            As[k][m] = (r < M) ? A[(size_t)r * K + k0 + k] : 0.f;
        }
        for (int idx = tid; idx < BK * BN; idx += 256) {
            int k = idx >> 6, n = idx & 63;
            int c = col0 + n;
            Bs[k][n] = (c < Nn) ? B[(size_t)(k0 + k) * Nn + c] : 0.f;
        }
        __syncthreads();
#pragma unroll
        for (int k = 0; k < BK; k++) {
            float4 av = *reinterpret_cast<const float4*>(&As[k][ty * 4]);
            float4 bv = *reinterpret_cast<const float4*>(&Bs[k][tx * 4]);
            float a[4] = {av.x, av.y, av.z, av.w};
            float b[4] = {bv.x, bv.y, bv.z, bv.w};
#pragma unroll
            for (int r = 0; r < 4; r++)
#pragma unroll
                for (int s = 0; s < 4; s++)
                    acc[r][s] = fmaf(a[r], b[s], acc[r][s]);
        }
        __syncthreads();
    }

#pragma unroll
    for (int r = 0; r < 4; r++) {
        int rr = row0 + ty * 4 + r;
        if (rr >= M) continue;
#pragma unroll
        for (int s = 0; s < 4; s++) {
            int cc = col0 + tx * 4 + s;
            if (cc >= Nn) continue;
            float v = acc[r][s];
            if (EPI == 2) {
                v += bias[cc] + addend[(size_t)rr * Nn + cc];
                v = fmaxf(v, 0.f);
            }
            Cmat[(size_t)rr * Nn + cc] = v;
        }
    }
}

// ---------------- zero accumulators ------------------------------------------
__global__ void zero_aggs() {
    int i = blockIdx.x * blockDim.x + threadIdx.x;
    if (i < N_CNT * H2) g_agg1[i] = 0.f;
    if (i < N_CNT * C_OUT) g_agg2[i] = 0.f;
}

// ---------------- edge pass 1: msg = ea @ P1[src] slices, scatter to agg1 ----
__global__ void edge_pass1(const float* __restrict__ ea) {
    int le = threadIdx.x >> 6;
    int o  = threadIdx.x & 63;
    int e  = blockIdx.x * 4 + le;
    __shared__ float sea[4][EDIM];
    if (e < E_CNT && o < EDIM) sea[le][o] = ea[(size_t)e * EDIM + o];
    __syncthreads();
    if (e >= E_CNT) return;
    int s = g_src[e], d = g_dst[e];
    const float* Prow = g_P1 + (size_t)s * NB1;
    float acc = Prow[EDIM * H2 + o];
#pragma unroll
    for (int k = 0; k < EDIM; k++)
        acc = fmaf(sea[le][k], Prow[k * H2 + o], acc);
    atomicAdd(&g_agg1[(size_t)d * H2 + o], acc);
}

// ---------------- edge pass 2 ------------------------------------------------
__global__ void edge_pass2(const float* __restrict__ ea) {
    int t = blockIdx.x * blockDim.x + threadIdx.x;
    if (t >= E_CNT * C_OUT) return;
    int e = t / C_OUT, c = t - e * C_OUT;
    int s = g_src[e], d = g_dst[e];
    const float* Prow = g_P2 + (size_t)s * NB2;
    float acc = Prow[EDIM * C_OUT + c];
#pragma unroll
    for (int k = 0; k < EDIM; k++)
        acc = fmaf(ea[(size_t)e * EDIM + k], Prow[k * C_OUT + c], acc);
    atomicAdd(&g_agg2[(size_t)d * C_OUT + c], acc);
}

// ---------------- final: z = agg2 + h2@root2 + bias2; log_softmax ------------
__global__ void final_kernel(const float* __restrict__ root2,
                             const float* __restrict__ bias2,
                             float* __restrict__ out) {
    int n = blockIdx.x * blockDim.x + threadIdx.x;
    if (n >= N_CNT) return;
    float z[C_OUT];
#pragma unroll
    for (int c = 0; c < C_OUT; c++) z[c] = g_agg2[(size_t)n * C_OUT + c] + bias2[c];
    const float* hrow = g_h2 + (size_t)n * H2;
    for (int i = 0; i < H2; i++) {
        float hv = hrow[i];
#pragma unroll
        for (int c = 0; c < C_OUT; c++)
            z[c] = fmaf(hv, root2[i * C_OUT + c], z[c]);
    }
    float m = z[0];
#pragma unroll
    for (int c = 1; c < C_OUT; c++) m = fmaxf(m, z[c]);
    float sum = 0.f;
#pragma unroll
    for (int c = 0; c < C_OUT; c++) sum += expf(z[c] - m);
    float lse = m + logf(sum);
#pragma unroll
    for (int c = 0; c < C_OUT; c++) out[(size_t)n * C_OUT + c] = z[c] - lse;
}

// ---------------- launch -----------------------------------------------------
extern "C" void kernel_launch(void* const* d_in, const int* in_sizes, int n_in,
                              void* d_out, int out_size) {
    const float* x     = (const float*)d_in[0];
    const float* ea    = (const float*)d_in[1];
    const void*  eidx  = d_in[2];
    const float* W1    = (const float*)d_in[3];
    const float* b1    = (const float*)d_in[4];
    const float* We1   = (const float*)d_in[5];
    const float* be1   = (const float*)d_in[6];
    const float* root1 = (const float*)d_in[7];
    const float* bias1 = (const float*)d_in[8];
    const float* We2   = (const float*)d_in[9];
    const float* be2   = (const float*)d_in[10];
    const float* root2 = (const float*)d_in[11];
    const float* bias2 = (const float*)d_in[12];
    float* out = (float*)d_out;

    void* p_agg1 = nullptr;
    float* ph = nullptr; float* ph2 = nullptr; float* pP1 = nullptr; float* pP2 = nullptr;
    float* pB1 = nullptr; float* pB2 = nullptr;
    cudaGetSymbolAddress(&p_agg1, g_agg1);
    cudaGetSymbolAddress((void**)&ph,  g_h);
    cudaGetSymbolAddress((void**)&ph2, g_h2);
    cudaGetSymbolAddress((void**)&pP1, g_P1);
    cudaGetSymbolAddress((void**)&pP2, g_P2);
    cudaGetSymbolAddress((void**)&pB1, g_B1);
    cudaGetSymbolAddress((void**)&pB2, g_B2);

    // launches 0-3
    detect_idx_kernel<<<1, 256>>>((const int*)eidx);
    convert_idx_kernel<<<(E_CNT + 255) / 256, 256>>>(eidx);
    build_B1_kernel<<<(H1 * NB1 + 255) / 256, 256>>>(We1, be1);
    build_B2_kernel<<<(H2 * NB2 + 255) / 256, 256>>>(We2, be2);

    dim3 blk(256);
    // launch 4: h = relu(x @ W1 + b1)   [10000,128], K=64
    {
        dim3 grid((H1 + GBN - 1) / GBN, (N_CNT + GBM - 1) / GBM);
        gemm128<1><<<grid, blk>>>(x, W1, ph, b1, N_CNT, H1, D_IN);
    }
    // launch 5 (ncu -s 5 -c 1 captures this): P1 = h @ B1   [10000,1088], K=128
    {
        dim3 grid((NB1 + GBN - 1) / GBN, (N_CNT + GBM - 1) / GBM);
        gemm128<0><<<grid, blk>>>(ph, pB1, pP1, nullptr, N_CNT, NB1, H1);
    }
    // zero accumulators (before edge passes)
    zero_aggs<<<(N_CNT * H2 + 255) / 256, 256>>>();
    // edge pass 1 -> agg1
    edge_pass1<<<(E_CNT + 3) / 4, 256>>>(ea);
    // h2 = relu(h @ root1 + bias1 + agg1)   [10000,64], K=128
    {
        dim3 grid((H2 + BN - 1) / BN, (N_CNT + BM - 1) / BM);
        gemm_ep<2><<<grid, blk>>>(ph, root1, ph2, bias1, (const float*)p_agg1,
                                  N_CNT, H2, H1);
    }
    // P2 = h2 @ B2   [10000,170], K=64
    {
        dim3 grid((NB2 + BN - 1) / BN, (N_CNT + BM - 1) / BM);
        gemm_ep<0><<<grid, blk>>>(ph2, pB2, pP2, nullptr, nullptr, N_CNT, NB2, H2);
    }
    // edge pass 2 -> agg2
    edge_pass2<<<(E_CNT * C_OUT + 255) / 256, 256>>>(ea);
    // final: z + log_softmax
    final_kernel<<<(N_CNT + 255) / 256, 256>>>(root2, bias2, out);
}

// round 5
// speedup vs baseline: 1.2562x; 1.0116x over previous
#include <cuda_runtime.h>
#include <cuda_bf16.h>
#include <math.h>
#include <stdint.h>

#define N_CNT 10000
#define E_CNT 30000
#define D_IN 64
#define EDIM 16
#define H1 128
#define H2 64
#define C_OUT 10

#define NB1 1088   // 16*64 + 64 (be1 columns folded in)
#define NB2 170    // 16*10 + 10 (be2 columns folded in)

#define MPAD 10112  // 79*128
#define NPAD 1152   // 9*128
#define KSPLIT 384  // 3*128 (bf16 split: [Ah|Al|Ah] x [Bh|Bh|Bl])

// ---------------- scratch (static device memory; no allocations) ------------
__device__ int   g_src[E_CNT];
__device__ int   g_dst[E_CNT];
__device__ float g_B2[H2 * NB2];
__device__ float g_h [N_CNT * H1];
__device__ __nv_bfloat16 g_Ab[(size_t)MPAD * KSPLIT];  // split h, K-major rows
__device__ __nv_bfloat16 g_Bb[(size_t)NPAD * KSPLIT];  // split B1, [n][k] rows
__device__ float g_P1[(size_t)N_CNT * NB1];            // ~43.5MB
__device__ float g_agg1[N_CNT * H2];
__device__ float g_h2 [N_CNT * H2];
__device__ float g_P2[(size_t)N_CNT * NB2];
__device__ float g_agg2[N_CNT * C_OUT];

// ---------------- helpers ----------------------------------------------------
__device__ __forceinline__ uint32_t smem_u32(const void* p) {
    uint32_t a;
    asm("{ .reg .u64 t; cvta.to.shared.u64 t, %1; cvt.u32.u64 %0, t; }"
        : "=r"(a) : "l"(p));
    return a;
}
__device__ __forceinline__ void ldmat_x4(uint32_t& r0, uint32_t& r1,
                                         uint32_t& r2, uint32_t& r3, uint32_t a) {
    asm volatile("ldmatrix.sync.aligned.m8n8.x4.shared.b16 {%0,%1,%2,%3}, [%4];"
                 : "=r"(r0), "=r"(r1), "=r"(r2), "=r"(r3) : "r"(a));
}
__device__ __forceinline__ void ldmat_x2(uint32_t& r0, uint32_t& r1, uint32_t a) {
    asm volatile("ldmatrix.sync.aligned.m8n8.x2.shared.b16 {%0,%1}, [%2];"
                 : "=r"(r0), "=r"(r1) : "r"(a));
}
__device__ __forceinline__ void mma_bf16(float* c, const uint32_t* a,
                                         const uint32_t* b) {
    asm volatile(
        "mma.sync.aligned.m16n8k16.row.col.f32.bf16.bf16.f32 "
        "{%0,%1,%2,%3}, {%4,%5,%6,%7}, {%8,%9}, {%0,%1,%2,%3};"
        : "+f"(c[0]), "+f"(c[1]), "+f"(c[2]), "+f"(c[3])
        : "r"(a[0]), "r"(a[1]), "r"(a[2]), "r"(a[3]), "r"(b[0]), "r"(b[1]));
}

// ---------------- launch 0: index detect + normalize (single block) ----------
__global__ void idx_fused(const void* eidx) {
    __shared__ int cnt;
    int tid = threadIdx.x;
    if (tid == 0) cnt = 0;
    __syncthreads();
    const int* ei = (const int*)eidx;
    int z = 0;
    for (int i = tid; i < 1024; i += blockDim.x)
        if (ei[2 * i + 1] == 0) z++;
    atomicAdd(&cnt, z);
    __syncthreads();
    int is64 = (cnt > 900);
    if (is64) {
        const long long* q = (const long long*)eidx;
        for (int i = tid; i < E_CNT; i += blockDim.x) {
            g_src[i] = (int)q[i];
            g_dst[i] = (int)q[E_CNT + i];
        }
    } else {
        const int* q = (const int*)eidx;
        for (int i = tid; i < E_CNT; i += blockDim.x) {
            g_src[i] = q[i];
            g_dst[i] = q[E_CNT + i];
        }
    }
}

// ---------------- launch 1: build split B' [NPAD][384] bf16 ------------------
__global__ void build_B1p(const float* __restrict__ We1,
                          const float* __restrict__ be1) {
    int idx = blockIdx.x * blockDim.x + threadIdx.x;
    if (idx >= NPAD * H1) return;
    int n = idx / H1, k = idx - n * H1;
    float v = 0.f;
    if (n < EDIM * H2) {
        int ke = n >> 6, o = n & 63;
        v = We1[(size_t)ke * (H1 * H2) + k * H2 + o];
    } else if (n < NB1) {
        v = be1[(size_t)k * H2 + (n - EDIM * H2)];
    }
    __nv_bfloat16 bh = __float2bfloat16(v);
    __nv_bfloat16 bl = __float2bfloat16(v - __bfloat162float(bh));
    __nv_bfloat16* row = g_Bb + (size_t)n * KSPLIT;
    row[k] = bh; row[128 + k] = bh; row[256 + k] = bl;
}

// ---------------- launch 2: build B2 -----------------------------------------
__global__ void build_B2_kernel(const float* __restrict__ We2,
                                const float* __restrict__ be2) {
    int idx = blockIdx.x * blockDim.x + threadIdx.x;
    if (idx >= H2 * NB2) return;
    int i = idx / NB2, col = idx - i * NB2;
    float v;
    if (col < EDIM * C_OUT) {
        int k = col / C_OUT, c = col - k * C_OUT;
        v = We2[(size_t)k * (H2 * C_OUT) + i * C_OUT + c];
    } else {
        v = be2[(size_t)i * C_OUT + (col - EDIM * C_OUT)];
    }
    g_B2[idx] = v;
}

// ---------------- big SGEMM (launch 3): h = relu(x@W1+b1) --------------------
#define GBM 128
#define GBN 128
#define GBK 8

template <int EPI>
__global__ __launch_bounds__(256, 2)
void gemm128(const float* __restrict__ A, const float* __restrict__ B,
             float* __restrict__ Cmat, const float* __restrict__ bias,
             int M, int Nn, int K) {
    __shared__ float As[2][GBK][GBM + 4];
    __shared__ float Bs[2][GBK][GBN];
    int tid = threadIdx.x;
    int tx = tid & 15, ty = tid >> 4;
    int ty4 = ty * 4, tx4 = tx * 4;
    int row0 = blockIdx.y * GBM;
    int col0 = blockIdx.x * GBN;
    int arow = tid >> 1;
    int akq  = (tid & 1) * 4;
    int brow = tid >> 5;
    int bcol = (tid & 31) * 4;
    int ga_row = row0 + arow;
    int gb_col = col0 + bcol;
    bool a_ok = (ga_row < M);
    bool b_ok = (gb_col < Nn);
    const float* Aptr = A + (size_t)(a_ok ? ga_row : 0) * K + akq;
    const float* Bptr = B + (size_t)brow * Nn + (b_ok ? gb_col : 0);
    float acc[8][8];
#pragma unroll
    for (int r = 0; r < 8; r++)
#pragma unroll
        for (int s = 0; s < 8; s++) acc[r][s] = 0.f;
    int nt = K / GBK;
    {
        float4 ra = a_ok ? *reinterpret_cast<const float4*>(Aptr)
                         : make_float4(0.f, 0.f, 0.f, 0.f);
        float4 rb = b_ok ? *reinterpret_cast<const float4*>(Bptr)
                         : make_float4(0.f, 0.f, 0.f, 0.f);
        As[0][akq + 0][arow] = ra.x;
        As[0][akq + 1][arow] = ra.y;
        As[0][akq + 2][arow] = ra.z;
        As[0][akq + 3][arow] = ra.w;
        *reinterpret_cast<float4*>(&Bs[0][brow][bcol]) = rb;
    }
    __syncthreads();
    for (int kt = 0; kt < nt; kt++) {
        int cur = kt & 1;
        float4 ra, rb;
        bool pre = (kt + 1 < nt);
        if (pre) {
            int k0 = (kt + 1) * GBK;
            ra = a_ok ? *reinterpret_cast<const float4*>(Aptr + k0)
                      : make_float4(0.f, 0.f, 0.f, 0.f);
            rb = b_ok ? *reinterpret_cast<const float4*>(Bptr + (size_t)k0 * Nn)
                      : make_float4(0.f, 0.f, 0.f, 0.f);
        }
#pragma unroll
        for (int k = 0; k < GBK; k++) {
            float4 a0 = *reinterpret_cast<const float4*>(&As[cur][k][ty4]);
            float4 a1 = *reinterpret_cast<const float4*>(&As[cur][k][ty4 + 64]);
            float4 b0 = *reinterpret_cast<const float4*>(&Bs[cur][k][tx4]);
            float4 b1 = *reinterpret_cast<const float4*>(&Bs[cur][k][tx4 + 64]);
            float a[8] = {a0.x, a0.y, a0.z, a0.w, a1.x, a1.y, a1.z, a1.w};
            float b[8] = {b0.x, b0.y, b0.z, b0.w, b1.x, b1.y, b1.z, b1.w};
#pragma unroll
            for (int r = 0; r < 8; r++)
#pragma unroll
                for (int s = 0; s < 8; s++)
                    acc[r][s] = fmaf(a[r], b[s], acc[r][s]);
        }
        if (pre) {
            int nxt = cur ^ 1;
            As[nxt][akq + 0][arow] = ra.x;
            As[nxt][akq + 1][arow] = ra.y;
            As[nxt][akq + 2][arow] = ra.z;
            As[nxt][akq + 3][arow] = ra.w;
            *reinterpret_cast<float4*>(&Bs[nxt][brow][bcol]) = rb;
            __syncthreads();
        }
    }
#pragma unroll
    for (int r = 0; r < 8; r++) {
        int rr = row0 + ty4 + (r & 3) + ((r >> 2) << 6);
        if (rr >= M) continue;
        float* crow = Cmat + (size_t)rr * Nn;
#pragma unroll
        for (int s = 0; s < 8; s++) {
            int cc = col0 + tx4 + (s & 3) + ((s >> 2) << 6);
            if (cc >= Nn) continue;
            float v = acc[r][s];
            if (EPI == 1) v = fmaxf(v + bias[cc], 0.f);
            crow[cc] = v;
        }
    }
}

// ---------------- launch 4: split h -> A' [MPAD][384] bf16 -------------------
__global__ void split_h_kernel() {
    int idx = blockIdx.x * blockDim.x + threadIdx.x;
    if (idx >= MPAD * H1) return;
    int m = idx >> 7, k = idx & 127;
    float v = (m < N_CNT) ? g_h[(size_t)m * H1 + k] : 0.f;
    __nv_bfloat16 ah = __float2bfloat16(v);
    __nv_bfloat16 al = __float2bfloat16(v - __bfloat162float(ah));
    __nv_bfloat16* row = g_Ab + (size_t)m * KSPLIT;
    row[k] = ah; row[128 + k] = al; row[256 + k] = ah;
}

// ---------------- launch 5: mma.sync bf16 GEMM: P1 = A' @ B'^T ---------------
// grid (9, 79), block 256 (8 warps, 2x4). CTA tile 128x128, warp tile 64x32.
// K chunks of 64, double-buffered smem, padded stride 72 (conflict-free ldmatrix).
#define KC 64
#define NKC (KSPLIT / KC)      // 6
#define SSTR 72                // bf16 elements per smem row

__global__ __launch_bounds__(256, 1)
void mma_gemm_p1() {
    extern __shared__ __nv_bfloat16 sm[];
    __nv_bfloat16* As = sm;                    // [2][128][SSTR]
    __nv_bfloat16* Bs = sm + 2 * 128 * SSTR;   // [2][128][SSTR]

    int tid = threadIdx.x;
    int wid = tid >> 5, lane = tid & 31;
    int row0 = blockIdx.y * 128;
    int col0 = blockIdx.x * 128;
    int wm0 = (wid >> 2) * 64;                 // warp M offset (0 or 64)
    int wn0 = (wid & 3) * 32;                  // warp N offset

    // global load mapping: 1024 uint4 per operand per chunk, 4 per thread
    int lrow = tid >> 1;                       // 0..127
    int lq   = (tid & 1) * 4;                  // uint4 index 0 or 4 (two per thread? no)
    // each thread loads rows {lrow}, uint4s {lq..lq+3}? That's 8 uint4 total for 2 threads/row.
    const uint4* Ag = reinterpret_cast<const uint4*>(g_Ab + (size_t)(row0 + lrow) * KSPLIT);
    const uint4* Bg = reinterpret_cast<const uint4*>(g_Bb + (size_t)(col0 + lrow) * KSPLIT);

    float acc[4][4][4];
#pragma unroll
    for (int i = 0; i < 4; i++)
#pragma unroll
        for (int j = 0; j < 4; j++)
#pragma unroll
            for (int q = 0; q < 4; q++) acc[i][j][q] = 0.f;

    // smem write base for this thread's 4 uint4 (8 bf16 each)
    // chunk c covers global k = c*64 .. +63  -> uint4 index c*8 + (lq + t)
    auto store_chunk = [&](int buf, const uint4* ra, const uint4* rb) {
#pragma unroll
        for (int t = 0; t < 4; t++) {
            int col8 = (lq + t) * 8;           // bf16 col within chunk
            *reinterpret_cast<uint4*>(&As[(buf * 128 + lrow) * SSTR + col8]) = ra[t];
            *reinterpret_cast<uint4*>(&Bs[(buf * 128 + lrow) * SSTR + col8]) = rb[t];
        }
    };

    // prologue: chunk 0
    {
        uint4 ra[4], rb[4];
#pragma unroll
        for (int t = 0; t < 4; t++) { ra[t] = Ag[lq + t]; rb[t] = Bg[lq + t]; }
        store_chunk(0, ra, rb);
    }
    __syncthreads();

    // ldmatrix smem addresses (fixed per thread, per buffer handled by offset)
    int a_r = wm0 + (lane & 7) + ((lane >> 3) & 1) * 8;
    int a_c = ((lane >> 4) & 1) * 8;
    int b_r = wn0 + (lane & 7);
    int b_c = ((lane >> 3) & 1) * 8;
    uint32_t As_base = smem_u32(As);
    uint32_t Bs_base = smem_u32(Bs);

    for (int c = 0; c < NKC; c++) {
        int cur = c & 1;
        uint4 ra[4], rb[4];
        bool pre = (c + 1 < NKC);
        if (pre) {
#pragma unroll
            for (int t = 0; t < 4; t++) {
                ra[t] = Ag[(c + 1) * 8 + lq + t];
                rb[t] = Bg[(c + 1) * 8 + lq + t];
            }
        }
        uint32_t Ab0 = As_base + (uint32_t)((cur * 128) * SSTR) * 2;
        uint32_t Bb0 = Bs_base + (uint32_t)((cur * 128) * SSTR) * 2;
#pragma unroll
        for (int ks = 0; ks < 4; ks++) {
            int k0 = ks * 16;
            uint32_t afr[4][4], bfr[4][2];
#pragma unroll
            for (int i = 0; i < 4; i++) {
                uint32_t addr = Ab0 + (uint32_t)((a_r + i * 16) * SSTR + k0 + a_c) * 2;
                ldmat_x4(afr[i][0], afr[i][1], afr[i][2], afr[i][3], addr);
            }
#pragma unroll
            for (int j = 0; j < 4; j++) {
                uint32_t addr = Bb0 + (uint32_t)((b_r + j * 8) * SSTR + k0 + b_c) * 2;
                ldmat_x2(bfr[j][0], bfr[j][1], addr);
            }
#pragma unroll
            for (int i = 0; i < 4; i++)
#pragma unroll
                for (int j = 0; j < 4; j++)
                    mma_bf16(acc[i][j], afr[i], bfr[j]);
        }
        if (pre) {
            store_chunk(cur ^ 1, ra, rb);
            __syncthreads();
        }
    }

    // epilogue: c0,c1 at (m = mt + lane/4, n = nt + 2*(lane%4)); c2,c3 at m+8
    int erow = lane >> 2;
    int ecol = (lane & 3) * 2;
#pragma unroll
    for (int i = 0; i < 4; i++) {
        int mg0 = row0 + wm0 + i * 16 + erow;
#pragma unroll
        for (int j = 0; j < 4; j++) {
            int ng = col0 + wn0 + j * 8 + ecol;
            if (ng >= NB1) continue;
            if (mg0 < N_CNT) {
                float2 v = make_float2(acc[i][j][0], acc[i][j][1]);
                *reinterpret_cast<float2*>(&g_P1[(size_t)mg0 * NB1 + ng]) = v;
            }
            if (mg0 + 8 < N_CNT) {
                float2 v = make_float2(acc[i][j][2], acc[i][j][3]);
                *reinterpret_cast<float2*>(&g_P1[(size_t)(mg0 + 8) * NB1 + ng]) = v;
            }
        }
    }
}

// ---------------- small fp32 tiled GEMM with epilogue ------------------------
#define BM 64
#define BN 64
#define BK 16

template <int EPI>
__global__ void gemm_ep(const float* __restrict__ A, const float* __restrict__ B,
                        float* __restrict__ Cmat, const float* __restrict__ bias,
                        const float* __restrict__ addend, int M, int Nn, int K) {
    __shared__ float As[BK][BM];
    __shared__ float Bs[BK][BN + 4];
    int tid = threadIdx.x;
    int tx = tid & 15, ty = tid >> 4;
    int row0 = blockIdx.y * BM;
    int col0 = blockIdx.x * BN;
    float acc[4][4] = {};
    for (int k0 = 0; k0 < K; k0 += BK) {
        for (int idx = tid; idx < BM * BK; idx += 256) {
            int m = idx >> 4, k = idx & 15;
            int r = row0 + m;
            As[k][m] = (r < M) ? A[(size_t)r * K + k0 + k] : 0.f;
        }
        for (int idx = tid; idx < BK * BN; idx += 256) {
            int k = idx >> 6, n = idx & 63;
            int c = col0 + n;
            Bs[k][n] = (c < Nn) ? B[(size_t)(k0 + k) * Nn + c] : 0.f;
        }
        __syncthreads();
#pragma unroll
        for (int k = 0; k < BK; k++) {
            float4 av = *reinterpret_cast<const float4*>(&As[k][ty * 4]);
            float4 bv = *reinterpret_cast<const float4*>(&Bs[k][tx * 4]);
            float a[4] = {av.x, av.y, av.z, av.w};
            float b[4] = {bv.x, bv.y, bv.z, bv.w};
#pragma unroll
            for (int r = 0; r < 4; r++)
#pragma unroll
                for (int s = 0; s < 4; s++)
                    acc[r][s] = fmaf(a[r], b[s], acc[r][s]);
        }
        __syncthreads();
    }
#pragma unroll
    for (int r = 0; r < 4; r++) {
        int rr = row0 + ty * 4 + r;
        if (rr >= M) continue;
#pragma unroll
        for (int s = 0; s < 4; s++) {
            int cc = col0 + tx * 4 + s;
            if (cc >= Nn) continue;
            float v = acc[r][s];
            if (EPI == 2) {
                v += bias[cc] + addend[(size_t)rr * Nn + cc];
                v = fmaxf(v, 0.f);
            }
            Cmat[(size_t)rr * Nn + cc] = v;
        }
    }
}

// ---------------- zero accumulators ------------------------------------------
__global__ void zero_aggs() {
    int i = blockIdx.x * blockDim.x + threadIdx.x;
    if (i < N_CNT * H2) g_agg1[i] = 0.f;
    if (i < N_CNT * C_OUT) g_agg2[i] = 0.f;
}

// ---------------- edge pass 1 ------------------------------------------------
__global__ void edge_pass1(const float* __restrict__ ea) {
    int le = threadIdx.x >> 6;
    int o  = threadIdx.x & 63;
    int e  = blockIdx.x * 4 + le;
    __shared__ float sea[4][EDIM];
    if (e < E_CNT && o < EDIM) sea[le][o] = ea[(size_t)e * EDIM + o];
    __syncthreads();
    if (e >= E_CNT) return;
    int s = g_src[e], d = g_dst[e];
    const float* Prow = g_P1 + (size_t)s * NB1;
    float acc = Prow[EDIM * H2 + o];
#pragma unroll
    for (int k = 0; k < EDIM; k++)
        acc = fmaf(sea[le][k], Prow[k * H2 + o], acc);
    atomicAdd(&g_agg1[(size_t)d * H2 + o], acc);
}

// ---------------- edge pass 2 ------------------------------------------------
__global__ void edge_pass2(const float* __restrict__ ea) {
    int t = blockIdx.x * blockDim.x + threadIdx.x;
    if (t >= E_CNT * C_OUT) return;
    int e = t / C_OUT, c = t - e * C_OUT;
    int s = g_src[e], d = g_dst[e];
    const float* Prow = g_P2 + (size_t)s * NB2;
    float acc = Prow[EDIM * C_OUT + c];
#pragma unroll
    for (int k = 0; k < EDIM; k++)
        acc = fmaf(ea[(size_t)e * EDIM + k], Prow[k * C_OUT + c], acc);
    atomicAdd(&g_agg2[(size_t)d * C_OUT + c], acc);
}

// ---------------- final ------------------------------------------------------
__global__ void final_kernel(const float* __restrict__ root2,
                             const float* __restrict__ bias2,
                             float* __restrict__ out) {
    int n = blockIdx.x * blockDim.x + threadIdx.x;
    if (n >= N_CNT) return;
    float z[C_OUT];
#pragma unroll
    for (int c = 0; c < C_OUT; c++) z[c] = g_agg2[(size_t)n * C_OUT + c] + bias2[c];
    const float* hrow = g_h2 + (size_t)n * H2;
    for (int i = 0; i < H2; i++) {
        float hv = hrow[i];
#pragma unroll
        for (int c = 0; c < C_OUT; c++)
            z[c] = fmaf(hv, root2[i * C_OUT + c], z[c]);
    }
    float m = z[0];
#pragma unroll
    for (int c = 1; c < C_OUT; c++) m = fmaxf(m, z[c]);
    float sum = 0.f;
#pragma unroll
    for (int c = 0; c < C_OUT; c++) sum += expf(z[c] - m);
    float lse = m + logf(sum);
#pragma unroll
    for (int c = 0; c < C_OUT; c++) out[(size_t)n * C_OUT + c] = z[c] - lse;
}

// ---------------- launch -----------------------------------------------------
extern "C" void kernel_launch(void* const* d_in, const int* in_sizes, int n_in,
                              void* d_out, int out_size) {
    const float* x     = (const float*)d_in[0];
    const float* ea    = (const float*)d_in[1];
    const void*  eidx  = d_in[2];
    const float* W1    = (const float*)d_in[3];
    const float* b1    = (const float*)d_in[4];
    const float* We1   = (const float*)d_in[5];
    const float* be1   = (const float*)d_in[6];
    const float* root1 = (const float*)d_in[7];
    const float* bias1 = (const float*)d_in[8];
    const float* We2   = (const float*)d_in[9];
    const float* be2   = (const float*)d_in[10];
    const float* root2 = (const float*)d_in[11];
    const float* bias2 = (const float*)d_in[12];
    float* out = (float*)d_out;

    void* p_agg1 = nullptr;
    float* ph = nullptr; float* ph2 = nullptr; float* pP2 = nullptr; float* pB2 = nullptr;
    cudaGetSymbolAddress(&p_agg1, g_agg1);
    cudaGetSymbolAddress((void**)&ph,  g_h);
    cudaGetSymbolAddress((void**)&ph2, g_h2);
    cudaGetSymbolAddress((void**)&pP2, g_P2);
    cudaGetSymbolAddress((void**)&pB2, g_B2);

    int mma_smem = 4 * 128 * SSTR * 2;  // A+B double-buffered bf16
    cudaFuncSetAttribute(mma_gemm_p1, cudaFuncAttributeMaxDynamicSharedMemorySize,
                         mma_smem);

    dim3 blk(256);
    // launch 0: index normalize
    idx_fused<<<1, 1024>>>(eidx);
    // launch 1: split B'
    build_B1p<<<(NPAD * H1 + 255) / 256, 256>>>(We1, be1);
    // launch 2: B2
    build_B2_kernel<<<(H2 * NB2 + 255) / 256, 256>>>(We2, be2);
    // launch 3: h = relu(x @ W1 + b1)
    {
        dim3 grid(1, (N_CNT + GBM - 1) / GBM);
        gemm128<1><<<grid, blk>>>(x, W1, ph, b1, N_CNT, H1, D_IN);
    }
    // launch 4: split h -> A'
    split_h_kernel<<<(MPAD * H1 + 255) / 256, 256>>>();
    // launch 5 (ncu target): P1 = A' @ B'^T  via mma.sync bf16
    {
        dim3 grid(NPAD / 128, MPAD / 128);
        mma_gemm_p1<<<grid, blk, mma_smem>>>();
    }
    // remaining
    zero_aggs<<<(N_CNT * H2 + 255) / 256, 256>>>();
    edge_pass1<<<(E_CNT + 3) / 4, 256>>>(ea);
    {
        dim3 grid((H2 + BN - 1) / BN, (N_CNT + BM - 1) / BM);
        gemm_ep<2><<<grid, blk>>>(ph, root1, ph2, bias1, (const float*)p_agg1,
                                  N_CNT, H2, H1);
    }
    {
        dim3 grid((NB2 + BN - 1) / BN, (N_CNT + BM - 1) / BM);
        gemm_ep<0><<<grid, blk>>>(ph2, pB2, pP2, nullptr, nullptr, N_CNT, NB2, H2);
    }
    edge_pass2<<<(E_CNT * C_OUT + 255) / 256, 256>>>(ea);
    final_kernel<<<(N_CNT + 255) / 256, 256>>>(root2, bias2, out);
}

// round 6
// speedup vs baseline: 1.5481x; 1.2324x over previous
#include <cuda_runtime.h>
#include <cuda_bf16.h>
#include <math.h>
#include <stdint.h>

#define N_CNT 10000
#define E_CNT 30000
#define D_IN 64
#define EDIM 16
#define H1 128
#define H2 64
#define C_OUT 10

#define NB1 1088
#define NB2 170

#define MPAD 10112  // 158*64 = 79*128
#define NPAD 1152   // 9*128
#define KSPLIT 384  // [Ah|Al|Ah] x [Bh|Bh|Bl]

// ---------------- scratch ----------------------------------------------------
__device__ int   g_src[E_CNT];
__device__ int   g_dst[E_CNT];
__device__ float g_B2[H2 * NB2];
__device__ float g_h [N_CNT * H1];
__device__ __nv_bfloat16 g_Ab[(size_t)MPAD * KSPLIT];
__device__ __nv_bfloat16 g_Bb[(size_t)NPAD * KSPLIT];
__device__ float g_P1[(size_t)N_CNT * NB1];
__device__ float g_agg1[N_CNT * H2];
__device__ float g_h2 [N_CNT * H2];
__device__ float g_P2[(size_t)N_CNT * NB2];
__device__ float g_agg2[N_CNT * C_OUT];

// ---------------- helpers ----------------------------------------------------
__device__ __forceinline__ uint32_t smem_u32(const void* p) {
    uint32_t a;
    asm("{ .reg .u64 t; cvta.to.shared.u64 t, %1; cvt.u32.u64 %0, t; }"
        : "=r"(a) : "l"(p));
    return a;
}
__device__ __forceinline__ void ldmat_x4(uint32_t& r0, uint32_t& r1,
                                         uint32_t& r2, uint32_t& r3, uint32_t a) {
    asm volatile("ldmatrix.sync.aligned.m8n8.x4.shared.b16 {%0,%1,%2,%3}, [%4];"
                 : "=r"(r0), "=r"(r1), "=r"(r2), "=r"(r3) : "r"(a));
}
__device__ __forceinline__ void ldmat_x2(uint32_t& r0, uint32_t& r1, uint32_t a) {
    asm volatile("ldmatrix.sync.aligned.m8n8.x2.shared.b16 {%0,%1}, [%2];"
                 : "=r"(r0), "=r"(r1) : "r"(a));
}
__device__ __forceinline__ void mma_bf16(float* c, const uint32_t* a,
                                         const uint32_t* b) {
    asm volatile(
        "mma.sync.aligned.m16n8k16.row.col.f32.bf16.bf16.f32 "
        "{%0,%1,%2,%3}, {%4,%5,%6,%7}, {%8,%9}, {%0,%1,%2,%3};"
        : "+f"(c[0]), "+f"(c[1]), "+f"(c[2]), "+f"(c[3])
        : "r"(a[0]), "r"(a[1]), "r"(a[2]), "r"(a[3]), "r"(b[0]), "r"(b[1]));
}
__device__ __forceinline__ void cp16(uint32_t dst, const void* src) {
    asm volatile("cp.async.cg.shared.global [%0], [%1], 16;"
                 :: "r"(dst), "l"(src));
}
#define CP_COMMIT() asm volatile("cp.async.commit_group;" ::: "memory")
#define CP_WAIT1()  asm volatile("cp.async.wait_group 1;" ::: "memory")
#define CP_WAIT0()  asm volatile("cp.async.wait_group 0;" ::: "memory")

// ---------------- launch 0: fused prep ---------------------------------------
// ranges: [0,E) idx | [.,+NPAD*H1) B1' | [+H2*NB2) B2 | zero agg1 | zero agg2
#define PREP_O1 (E_CNT)
#define PREP_O2 (PREP_O1 + NPAD * H1)
#define PREP_O3 (PREP_O2 + H2 * NB2)
#define PREP_O4 (PREP_O3 + N_CNT * H2)
#define PREP_TOT (PREP_O4 + N_CNT * C_OUT)

__global__ void prep_kernel(const void* eidx,
                            const float* __restrict__ We1,
                            const float* __restrict__ be1,
                            const float* __restrict__ We2,
                            const float* __restrict__ be2) {
    int idx = blockIdx.x * blockDim.x + threadIdx.x;
    if (idx >= PREP_TOT) return;
    if (idx < PREP_O1) {
        const int* p = (const int*)eidx;
        bool is64 = true;
#pragma unroll
        for (int j = 0; j < 8; j++) is64 &= (p[2 * j + 1] == 0);
        if (is64) {
            const long long* q = (const long long*)eidx;
            g_src[idx] = (int)q[idx];
            g_dst[idx] = (int)q[E_CNT + idx];
        } else {
            g_src[idx] = p[idx];
            g_dst[idx] = p[E_CNT + idx];
        }
    } else if (idx < PREP_O2) {
        int t = idx - PREP_O1;
        int n = t / H1, k = t - n * H1;
        float v = 0.f;
        if (n < EDIM * H2) {
            int ke = n >> 6, o = n & 63;
            v = We1[(size_t)ke * (H1 * H2) + k * H2 + o];
        } else if (n < NB1) {
            v = be1[(size_t)k * H2 + (n - EDIM * H2)];
        }
        __nv_bfloat16 bh = __float2bfloat16(v);
        __nv_bfloat16 bl = __float2bfloat16(v - __bfloat162float(bh));
        __nv_bfloat16* row = g_Bb + (size_t)n * KSPLIT;
        row[k] = bh; row[128 + k] = bh; row[256 + k] = bl;
    } else if (idx < PREP_O3) {
        int t = idx - PREP_O2;
        int i = t / NB2, col = t - i * NB2;
        float v;
        if (col < EDIM * C_OUT) {
            int k = col / C_OUT, c = col - k * C_OUT;
            v = We2[(size_t)k * (H2 * C_OUT) + i * C_OUT + c];
        } else {
            v = be2[(size_t)i * C_OUT + (col - EDIM * C_OUT)];
        }
        g_B2[t] = v;
    } else if (idx < PREP_O4) {
        g_agg1[idx - PREP_O3] = 0.f;
    } else {
        g_agg2[idx - PREP_O4] = 0.f;
    }
}

// ---------------- launch 1: gemm_h: h=relu(x@W1+b1) + bf16 split epilogue ----
// tile 64x128, grid 158, block 256 (warp: ty=tid>>5 rowgrp, tx=tid&31 colgrp)
#define HPAD_W 132
#define HPAD_A 68
#define GH_SMEM ((64 * HPAD_W + 64 * HPAD_A) * 4)

__global__ __launch_bounds__(256, 2)
void gemm_h(const float* __restrict__ x, const float* __restrict__ W1,
            const float* __restrict__ b1) {
    extern __shared__ float fsm[];
    float* Ws = fsm;                 // [64][132]
    float* As = fsm + 64 * HPAD_W;   // [k][m] transposed, [64][68]
    int tid = threadIdx.x;
    int tx = tid & 31, ty = tid >> 5;
    int m0 = blockIdx.x * 64;

    // load W1 [64][128]
    for (int i = tid; i < 2048; i += 256) {
        int k = i >> 5, n4 = (i & 31) * 4;
        float4 v = *reinterpret_cast<const float4*>(&W1[k * H1 + n4]);
        *reinterpret_cast<float4*>(&Ws[k * HPAD_W + n4]) = v;
    }
    // load x tile [64][64] -> As[k][m]
    for (int i = tid; i < 1024; i += 256) {
        int m = i >> 4, k4 = (i & 15) * 4;
        float4 v = (m0 + m < N_CNT)
            ? *reinterpret_cast<const float4*>(&x[(size_t)(m0 + m) * D_IN + k4])
            : make_float4(0.f, 0.f, 0.f, 0.f);
        As[(k4 + 0) * HPAD_A + m] = v.x;
        As[(k4 + 1) * HPAD_A + m] = v.y;
        As[(k4 + 2) * HPAD_A + m] = v.z;
        As[(k4 + 3) * HPAD_A + m] = v.w;
    }
    __syncthreads();

    float acc[8][4];
#pragma unroll
    for (int r = 0; r < 8; r++)
#pragma unroll
        for (int s = 0; s < 4; s++) acc[r][s] = 0.f;

#pragma unroll 4
    for (int k = 0; k < 64; k++) {
        float4 a0 = *reinterpret_cast<const float4*>(&As[k * HPAD_A + ty * 8]);
        float4 a1 = *reinterpret_cast<const float4*>(&As[k * HPAD_A + ty * 8 + 4]);
        float4 w  = *reinterpret_cast<const float4*>(&Ws[k * HPAD_W + tx * 4]);
        float a[8] = {a0.x, a0.y, a0.z, a0.w, a1.x, a1.y, a1.z, a1.w};
        float ww[4] = {w.x, w.y, w.z, w.w};
#pragma unroll
        for (int r = 0; r < 8; r++)
#pragma unroll
            for (int s = 0; s < 4; s++)
                acc[r][s] = fmaf(a[r], ww[s], acc[r][s]);
    }

    float bv[4];
#pragma unroll
    for (int s = 0; s < 4; s++) bv[s] = b1[tx * 4 + s];

#pragma unroll
    for (int r = 0; r < 8; r++) {
        int m = m0 + ty * 8 + r;
        float v[4];
#pragma unroll
        for (int s = 0; s < 4; s++) v[s] = fmaxf(acc[r][s] + bv[s], 0.f);
        if (m < N_CNT)
            *reinterpret_cast<float4*>(&g_h[(size_t)m * H1 + tx * 4]) =
                make_float4(v[0], v[1], v[2], v[3]);
        // bf16 split rows (padded rows harmless: P1 rows >= N_CNT never read)
        __nv_bfloat16 ah[4], al[4];
#pragma unroll
        for (int s = 0; s < 4; s++) {
            ah[s] = __float2bfloat16(v[s]);
            al[s] = __float2bfloat16(v[s] - __bfloat162float(ah[s]));
        }
        __nv_bfloat16* row = g_Ab + (size_t)m * KSPLIT + tx * 4;
        uint32_t hi0 = ((uint32_t)__bfloat16_as_ushort(ah[1]) << 16) |
                       __bfloat16_as_ushort(ah[0]);
        uint32_t hi1 = ((uint32_t)__bfloat16_as_ushort(ah[3]) << 16) |
                       __bfloat16_as_ushort(ah[2]);
        uint32_t lo0 = ((uint32_t)__bfloat16_as_ushort(al[1]) << 16) |
                       __bfloat16_as_ushort(al[0]);
        uint32_t lo1 = ((uint32_t)__bfloat16_as_ushort(al[3]) << 16) |
                       __bfloat16_as_ushort(al[2]);
        *reinterpret_cast<uint2*>(row)       = make_uint2(hi0, hi1);
        *reinterpret_cast<uint2*>(row + 128) = make_uint2(lo0, lo1);
        *reinterpret_cast<uint2*>(row + 256) = make_uint2(hi0, hi1);
    }
}

// ---------------- launch 2: mma.sync bf16 GEMM with cp.async pipeline --------
#define KC 64
#define NKC (KSPLIT / KC)      // 6
#define SSTR 72
#define MMA_SMEM (4 * 128 * SSTR * 2)

__global__ __launch_bounds__(256, 2)
void mma_gemm_p1() {
    extern __shared__ __nv_bfloat16 sm[];
    __nv_bfloat16* As = sm;                    // [2][128][SSTR]
    __nv_bfloat16* Bs = sm + 2 * 128 * SSTR;

    int tid = threadIdx.x;
    int wid = tid >> 5, lane = tid & 31;
    int row0 = blockIdx.y * 128;
    int col0 = blockIdx.x * 128;
    int wm0 = (wid >> 2) * 64;
    int wn0 = (wid & 3) * 32;

    int lrow = tid >> 1;
    int lq   = (tid & 1) * 4;
    const char* Ag = (const char*)(g_Ab) + (size_t)(row0 + lrow) * (KSPLIT * 2);
    const char* Bg = (const char*)(g_Bb) + (size_t)(col0 + lrow) * (KSPLIT * 2);
    uint32_t As_base = smem_u32(As);
    uint32_t Bs_base = smem_u32(Bs);
    uint32_t a_st = As_base + (uint32_t)(lrow * SSTR + lq * 8) * 2;
    uint32_t b_st = Bs_base + (uint32_t)(lrow * SSTR + lq * 8) * 2;
    const uint32_t buf_stride = 128 * SSTR * 2;

    auto issue = [&](int c, int buf) {
#pragma unroll
        for (int t = 0; t < 4; t++) {
            cp16(a_st + buf * buf_stride + t * 16, Ag + c * 128 + (lq + t) * 16);
            cp16(b_st + buf * buf_stride + t * 16, Bg + c * 128 + (lq + t) * 16);
        }
    };

    float acc[4][4][4];
#pragma unroll
    for (int i = 0; i < 4; i++)
#pragma unroll
        for (int j = 0; j < 4; j++)
#pragma unroll
            for (int q = 0; q < 4; q++) acc[i][j][q] = 0.f;

    issue(0, 0);
    CP_COMMIT();

    int a_r = wm0 + (lane & 7) + ((lane >> 3) & 1) * 8;
    int a_c = ((lane >> 4) & 1) * 8;
    int b_r = wn0 + (lane & 7);
    int b_c = ((lane >> 3) & 1) * 8;

    for (int c = 0; c < NKC; c++) {
        int cur = c & 1;
        bool pre = (c + 1 < NKC);
        if (pre) { issue(c + 1, cur ^ 1); CP_COMMIT(); CP_WAIT1(); }
        else     { CP_WAIT0(); }
        __syncthreads();
        uint32_t Ab0 = As_base + (uint32_t)cur * buf_stride;
        uint32_t Bb0 = Bs_base + (uint32_t)cur * buf_stride;
#pragma unroll
        for (int ks = 0; ks < 4; ks++) {
            int k0 = ks * 16;
            uint32_t afr[4][4], bfr[4][2];
#pragma unroll
            for (int i = 0; i < 4; i++) {
                uint32_t addr = Ab0 + (uint32_t)((a_r + i * 16) * SSTR + k0 + a_c) * 2;
                ldmat_x4(afr[i][0], afr[i][1], afr[i][2], afr[i][3], addr);
            }
#pragma unroll
            for (int j = 0; j < 4; j++) {
                uint32_t addr = Bb0 + (uint32_t)((b_r + j * 8) * SSTR + k0 + b_c) * 2;
                ldmat_x2(bfr[j][0], bfr[j][1], addr);
            }
#pragma unroll
            for (int i = 0; i < 4; i++)
#pragma unroll
                for (int j = 0; j < 4; j++)
                    mma_bf16(acc[i][j], afr[i], bfr[j]);
        }
        __syncthreads();
    }

    int erow = lane >> 2;
    int ecol = (lane & 3) * 2;
#pragma unroll
    for (int i = 0; i < 4; i++) {
        int mg0 = row0 + wm0 + i * 16 + erow;
#pragma unroll
        for (int j = 0; j < 4; j++) {
            int ng = col0 + wn0 + j * 8 + ecol;
            if (ng >= NB1) continue;
            if (mg0 < N_CNT)
                *reinterpret_cast<float2*>(&g_P1[(size_t)mg0 * NB1 + ng]) =
                    make_float2(acc[i][j][0], acc[i][j][1]);
            if (mg0 + 8 < N_CNT)
                *reinterpret_cast<float2*>(&g_P1[(size_t)(mg0 + 8) * NB1 + ng]) =
                    make_float2(acc[i][j][2], acc[i][j][3]);
        }
    }
}

// ---------------- small fp32 tiled GEMM with epilogue ------------------------
#define BM 64
#define BN 64
#define BK 16

template <int EPI>
__global__ void gemm_ep(const float* __restrict__ A, const float* __restrict__ B,
                        float* __restrict__ Cmat, const float* __restrict__ bias,
                        const float* __restrict__ addend, int M, int Nn, int K) {
    __shared__ float As[BK][BM];
    __shared__ float Bs[BK][BN + 4];
    int tid = threadIdx.x;
    int tx = tid & 15, ty = tid >> 4;
    int row0 = blockIdx.y * BM;
    int col0 = blockIdx.x * BN;
    float acc[4][4] = {};
    for (int k0 = 0; k0 < K; k0 += BK) {
        for (int idx = tid; idx < BM * BK; idx += 256) {
            int m = idx >> 4, k = idx & 15;
            int r = row0 + m;
            As[k][m] = (r < M) ? A[(size_t)r * K + k0 + k] : 0.f;
        }
        for (int idx = tid; idx < BK * BN; idx += 256) {
            int k = idx >> 6, n = idx & 63;
            int c = col0 + n;
            Bs[k][n] = (c < Nn) ? B[(size_t)(k0 + k) * Nn + c] : 0.f;
        }
        __syncthreads();
#pragma unroll
        for (int k = 0; k < BK; k++) {
            float4 av = *reinterpret_cast<const float4*>(&As[k][ty * 4]);
            float4 bv = *reinterpret_cast<const float4*>(&Bs[k][tx * 4]);
            float a[4] = {av.x, av.y, av.z, av.w};
            float b[4] = {bv.x, bv.y, bv.z, bv.w};
#pragma unroll
            for (int r = 0; r < 4; r++)
#pragma unroll
                for (int s = 0; s < 4; s++)
                    acc[r][s] = fmaf(a[r], b[s], acc[r][s]);
        }
        __syncthreads();
    }
#pragma unroll
    for (int r = 0; r < 4; r++) {
        int rr = row0 + ty * 4 + r;
        if (rr >= M) continue;
#pragma unroll
        for (int s = 0; s < 4; s++) {
            int cc = col0 + tx * 4 + s;
            if (cc >= Nn) continue;
            float v = acc[r][s];
            if (EPI == 2) {
                v += bias[cc] + addend[(size_t)rr * Nn + cc];
                v = fmaxf(v, 0.f);
            }
            Cmat[(size_t)rr * Nn + cc] = v;
        }
    }
}

// ---------------- edge pass 1 ------------------------------------------------
__global__ void edge_pass1(const float* __restrict__ ea) {
    int le = threadIdx.x >> 6;
    int o  = threadIdx.x & 63;
    int e  = blockIdx.x * 4 + le;
    __shared__ float sea[4][EDIM];
    if (e < E_CNT && o < EDIM) sea[le][o] = ea[(size_t)e * EDIM + o];
    __syncthreads();
    if (e >= E_CNT) return;
    int s = g_src[e], d = g_dst[e];
    const float* Prow = g_P1 + (size_t)s * NB1;
    float acc = Prow[EDIM * H2 + o];
#pragma unroll
    for (int k = 0; k < EDIM; k++)
        acc = fmaf(sea[le][k], Prow[k * H2 + o], acc);
    atomicAdd(&g_agg1[(size_t)d * H2 + o], acc);
}

// ---------------- edge pass 2 ------------------------------------------------
__global__ void edge_pass2(const float* __restrict__ ea) {
    int t = blockIdx.x * blockDim.x + threadIdx.x;
    if (t >= E_CNT * C_OUT) return;
    int e = t / C_OUT, c = t - e * C_OUT;
    int s = g_src[e], d = g_dst[e];
    const float* Prow = g_P2 + (size_t)s * NB2;
    float acc = Prow[EDIM * C_OUT + c];
#pragma unroll
    for (int k = 0; k < EDIM; k++)
        acc = fmaf(ea[(size_t)e * EDIM + k], Prow[k * C_OUT + c], acc);
    atomicAdd(&g_agg2[(size_t)d * C_OUT + c], acc);
}

// ---------------- final ------------------------------------------------------
__global__ void final_kernel(const float* __restrict__ root2,
                             const float* __restrict__ bias2,
                             float* __restrict__ out) {
    int n = blockIdx.x * blockDim.x + threadIdx.x;
    if (n >= N_CNT) return;
    float z[C_OUT];
#pragma unroll
    for (int c = 0; c < C_OUT; c++) z[c] = g_agg2[(size_t)n * C_OUT + c] + bias2[c];
    const float* hrow = g_h2 + (size_t)n * H2;
    for (int i = 0; i < H2; i++) {
        float hv = hrow[i];
#pragma unroll
        for (int c = 0; c < C_OUT; c++)
            z[c] = fmaf(hv, root2[i * C_OUT + c], z[c]);
    }
    float m = z[0];
#pragma unroll
    for (int c = 1; c < C_OUT; c++) m = fmaxf(m, z[c]);
    float sum = 0.f;
#pragma unroll
    for (int c = 0; c < C_OUT; c++) sum += expf(z[c] - m);
    float lse = m + logf(sum);
#pragma unroll
    for (int c = 0; c < C_OUT; c++) out[(size_t)n * C_OUT + c] = z[c] - lse;
}

// ---------------- launch -----------------------------------------------------
extern "C" void kernel_launch(void* const* d_in, const int* in_sizes, int n_in,
                              void* d_out, int out_size) {
    const float* x     = (const float*)d_in[0];
    const float* ea    = (const float*)d_in[1];
    const void*  eidx  = d_in[2];
    const float* W1    = (const float*)d_in[3];
    const float* b1    = (const float*)d_in[4];
    const float* We1   = (const float*)d_in[5];
    const float* be1   = (const float*)d_in[6];
    const float* root1 = (const float*)d_in[7];
    const float* bias1 = (const float*)d_in[8];
    const float* We2   = (const float*)d_in[9];
    const float* be2   = (const float*)d_in[10];
    const float* root2 = (const float*)d_in[11];
    const float* bias2 = (const float*)d_in[12];
    float* out = (float*)d_out;

    void* p_agg1 = nullptr;
    float* ph = nullptr; float* ph2 = nullptr; float* pP2 = nullptr; float* pB2 = nullptr;
    cudaGetSymbolAddress(&p_agg1, g_agg1);
    cudaGetSymbolAddress((void**)&ph,  g_h);
    cudaGetSymbolAddress((void**)&ph2, g_h2);
    cudaGetSymbolAddress((void**)&pP2, g_P2);
    cudaGetSymbolAddress((void**)&pB2, g_B2);

    cudaFuncSetAttribute(mma_gemm_p1, cudaFuncAttributeMaxDynamicSharedMemorySize,
                         MMA_SMEM);
    cudaFuncSetAttribute(gemm_h, cudaFuncAttributeMaxDynamicSharedMemorySize,
                         GH_SMEM);

    dim3 blk(256);
    // 0: fused prep
    prep_kernel<<<(PREP_TOT + 255) / 256, 256>>>(eidx, We1, be1, We2, be2);
    // 1: h = relu(x@W1+b1) + bf16 split
    gemm_h<<<MPAD / 64, blk, GH_SMEM>>>(x, W1, b1);
    // 2: P1 = A' @ B'^T
    {
        dim3 grid(NPAD / 128, MPAD / 128);
        mma_gemm_p1<<<grid, blk, MMA_SMEM>>>();
    }
    // 3: edge pass 1
    edge_pass1<<<(E_CNT + 3) / 4, 256>>>(ea);
    // 4: h2 = relu(h@root1 + bias1 + agg1)
    {
        dim3 grid(1, (N_CNT + BM - 1) / BM);
        gemm_ep<2><<<grid, blk>>>(ph, root1, ph2, bias1, (const float*)p_agg1,
                                  N_CNT, H2, H1);
    }
    // 5: P2 = h2 @ B2
    {
        dim3 grid((NB2 + BN - 1) / BN, (N_CNT + BM - 1) / BM);
        gemm_ep<0><<<grid, blk>>>(ph2, pB2, pP2, nullptr, nullptr, N_CNT, NB2, H2);
    }
    // 6: edge pass 2
    edge_pass2<<<(E_CNT * C_OUT + 255) / 256, 256>>>(ea);
    // 7: final
    final_kernel<<<(N_CNT + 255) / 256, 256>>>(root2, bias2, out);
}